// round 4
// baseline (speedup 1.0000x reference)
#include <cuda_runtime.h>

// ---------------- problem-size constants ----------------
#define NMAX 50000
#define EMAX 800000
#define F1   64
#define F2   32
#define DIN  128
#define DOUT 128

#define SCAN_ELEM 1024

// ---------------- device scratch ----------------
__device__ int   g_cnt[NMAX];
__device__ int   g_rowptr[NMAX + 1];
__device__ int   g_pos[NMAX];
__device__ float g_dinv[NMAX];
__device__ int2  g_edge[EMAX];
__device__ float g_h1[NMAX * F1];
__device__ float g_a1[NMAX * F1];
__device__ float g_h2[NMAX * F2];
__device__ float g_a2[NMAX * F2];
__device__ int   g_is64;
__device__ int   g_bsum[64];
__device__ int   g_boff[64];

// ---------------- f32x2 packed FMA helper ----------------
__device__ __forceinline__ void fma2(unsigned long long& d,
                                     unsigned long long a,
                                     unsigned long long b) {
    asm("fma.rn.f32x2 %0, %1, %2, %0;" : "+l"(d) : "l"(a), "l"(b));
}
__device__ __forceinline__ float lo32(unsigned long long v) {
    return __uint_as_float((unsigned)(v & 0xffffffffull));
}
__device__ __forceinline__ float hi32(unsigned long long v) {
    return __uint_as_float((unsigned)(v >> 32));
}

// ---------------- detect dtype + zero counters (merged) ----------------
__global__ void detect_zero_kernel(const int* __restrict__ w, int E, int n) {
    int i = blockIdx.x * blockDim.x + threadIdx.x;
    if (i < n) g_cnt[i] = 0;
    if (blockIdx.x == 0) {
        __shared__ int any_nonzero;
        if (threadIdx.x == 0) any_nonzero = 0;
        __syncthreads();
        int stride = (2 * E) / 512;
        int idx = 2 * (threadIdx.x * stride) + 1;
        if (w[idx] != 0) atomicOr(&any_nonzero, 1);
        __syncthreads();
        if (threadIdx.x == 0) g_is64 = any_nonzero ? 0 : 1;
    }
}

__global__ void count_kernel(const int* __restrict__ w, int E) {
    int e = blockIdx.x * blockDim.x + threadIdx.x;
    if (e >= E) return;
    int d = g_is64 ? w[2 * (E + e)] : w[E + e];
    atomicAdd(&g_cnt[d], 1);
}

// ---- scan phase 1: per-block reduce
__global__ void scan1_kernel(int n) {
    const int tid = threadIdx.x;
    const int base = blockIdx.x * SCAN_ELEM + tid * 4;
    int s = 0;
#pragma unroll
    for (int i = 0; i < 4; i++) {
        int idx = base + i;
        if (idx < n) s += g_cnt[idx];
    }
#pragma unroll
    for (int o = 16; o; o >>= 1) s += __shfl_down_sync(0xffffffffu, s, o);
    __shared__ int ws[8];
    if ((tid & 31) == 0) ws[tid >> 5] = s;
    __syncthreads();
    if (tid < 8) {
        int t = ws[tid];
#pragma unroll
        for (int o = 4; o; o >>= 1) t += __shfl_down_sync(0xffu, t, o);
        if (tid == 0) g_bsum[blockIdx.x] = t;
    }
}

// ---- scan phase 2: scan of block sums
__global__ void scan2_kernel(int nblk) {
    __shared__ int sh[64];
    const int t = threadIdx.x;
    int v = (t < nblk) ? g_bsum[t] : 0;
    sh[t] = v;
    __syncthreads();
    for (int o = 1; o < 64; o <<= 1) {
        int u = (t >= o) ? sh[t - o] : 0;
        __syncthreads();
        sh[t] += u;
        __syncthreads();
    }
    if (t < nblk) g_boff[t] = sh[t] - v;
}

// ---- scan phase 3: rowptr/pos + dinv (fused)
__global__ void scan3_kernel(int n, int E) {
    const int tid = threadIdx.x;
    const int lane = tid & 31;
    const int wid = tid >> 5;
    const int base = blockIdx.x * SCAN_ELEM + tid * 4;

    int a[4];
    int tsum = 0;
#pragma unroll
    for (int i = 0; i < 4; i++) {
        int idx = base + i;
        a[i] = (idx < n) ? g_cnt[idx] : 0;
        tsum += a[i];
    }
    int x = tsum;
#pragma unroll
    for (int o = 1; o < 32; o <<= 1) {
        int y = __shfl_up_sync(0xffffffffu, x, o);
        if (lane >= o) x += y;
    }
    const int wex = x - tsum;

    __shared__ int ws[8];
    if (lane == 31) ws[wid] = x;
    __syncthreads();
    if (tid < 8) {
        int orig = ws[tid];
        int t = orig;
#pragma unroll
        for (int o = 1; o < 8; o <<= 1) {
            int y = __shfl_up_sync(0xffu, t, o);
            if (tid >= o) t += y;
        }
        ws[tid] = t - orig;
    }
    __syncthreads();

    int run = g_boff[blockIdx.x] + ws[wid] + wex;
#pragma unroll
    for (int i = 0; i < 4; i++) {
        int idx = base + i;
        if (idx < n) {
            g_rowptr[idx] = run;
            g_pos[idx] = run;
            g_dinv[idx] = rsqrtf((float)(a[i] + 1));
        }
        run += a[i];
    }
    if (blockIdx.x == 0 && tid == 0) g_rowptr[n] = E;
}

__global__ void scatter_kernel(const int* __restrict__ w, int E) {
    int e = blockIdx.x * blockDim.x + threadIdx.x;
    if (e >= E) return;
    int s, d;
    if (g_is64) { s = w[2 * e]; d = w[2 * (E + e)]; }
    else        { s = w[e];     d = w[E + e];       }
    float wn = g_dinv[s] * g_dinv[d];
    int p = atomicAdd(&g_pos[d], 1);
    g_edge[p] = make_int2(s, __float_as_int(wn));
}

// ---------------- f32x2 register-tiled GEMM ----------------
// block tile TM=128 nodes x TN cols; per-thread 8 nodes x 4 cols via FFMA2.
// Xs transposed [k][node]; Wdup [k][2*col] duplicated pairs for pack-free b.
template<int KIN, int KOUT, int TN, bool INACT, bool OBIAS>
__global__ void __launch_bounds__((TN / 4) * 16)
gemm_rt(const float* __restrict__ A, const float* __restrict__ W,
        const float* __restrict__ ib, const float* __restrict__ ob,
        float* __restrict__ H, int n)
{
    constexpr int TM = 128;
    constexpr int TK = (KIN < 16) ? KIN : 16;
    constexpr int NTX = TN / 4;           // col groups
    constexpr int NTY = TM / 8;           // node groups (16)
    constexpr int NTH = NTX * NTY;
    constexpr int XPITCH = TM + 8;        // float pitch, keeps 16B alignment

    __shared__ float Xs[TK * XPITCH];
    __shared__ float Wd[TK * TN * 2];

    const int tid = threadIdx.x;
    const int tx = tid % NTX;
    const int ty = tid / NTX;
    const int nb = blockIdx.x * TM;
    const int jn = blockIdx.y * TN;
    const int valid = min(TM, n - nb);

    unsigned long long acc[4][4];         // [node-pair][col]
#pragma unroll
    for (int i = 0; i < 4; i++)
#pragma unroll
        for (int j = 0; j < 4; j++) acc[i][j] = 0ull;

    for (int kt = 0; kt < KIN; kt += TK) {
        // X tile: load float4 rows, transpose into Xs[k][node] (+bias/relu)
#pragma unroll
        for (int idx = tid; idx < TM * TK / 4; idx += NTH) {
            int r  = idx / (TK / 4);
            int kq = idx % (TK / 4);
            float4 v = make_float4(0.f, 0.f, 0.f, 0.f);
            if (r < valid)
                v = *reinterpret_cast<const float4*>(
                        A + (long long)(nb + r) * KIN + kt + kq * 4);
            if (INACT) {
                const float4 bb = *reinterpret_cast<const float4*>(ib + kt + kq * 4);
                v.x = fmaxf(v.x + bb.x, 0.f);
                v.y = fmaxf(v.y + bb.y, 0.f);
                v.z = fmaxf(v.z + bb.z, 0.f);
                v.w = fmaxf(v.w + bb.w, 0.f);
            }
            Xs[(kq * 4 + 0) * XPITCH + r] = v.x;
            Xs[(kq * 4 + 1) * XPITCH + r] = v.y;
            Xs[(kq * 4 + 2) * XPITCH + r] = v.z;
            Xs[(kq * 4 + 3) * XPITCH + r] = v.w;
        }
        // W tile: duplicated store {w,w}
#pragma unroll
        for (int idx = tid; idx < TK * TN / 4; idx += NTH) {
            int kk = idx / (TN / 4);
            int jq = idx % (TN / 4);
            float4 v = *reinterpret_cast<const float4*>(
                           W + (long long)(kt + kk) * KOUT + jn + jq * 4);
            float* p = Wd + kk * TN * 2 + jq * 8;
            p[0] = v.x; p[1] = v.x;
            p[2] = v.y; p[3] = v.y;
            p[4] = v.z; p[5] = v.z;
            p[6] = v.w; p[7] = v.w;
        }
        __syncthreads();

#pragma unroll
        for (int kk = 0; kk < TK; kk++) {
            const ulonglong2 a0 = *reinterpret_cast<const ulonglong2*>(Xs + kk * XPITCH + ty * 8);
            const ulonglong2 a1 = *reinterpret_cast<const ulonglong2*>(Xs + kk * XPITCH + ty * 8 + 4);
            const ulonglong2 b0 = *reinterpret_cast<const ulonglong2*>(Wd + kk * TN * 2 + tx * 8);
            const ulonglong2 b1 = *reinterpret_cast<const ulonglong2*>(Wd + kk * TN * 2 + tx * 8 + 4);
            fma2(acc[0][0], a0.x, b0.x); fma2(acc[0][1], a0.x, b0.y);
            fma2(acc[0][2], a0.x, b1.x); fma2(acc[0][3], a0.x, b1.y);
            fma2(acc[1][0], a0.y, b0.x); fma2(acc[1][1], a0.y, b0.y);
            fma2(acc[1][2], a0.y, b1.x); fma2(acc[1][3], a0.y, b1.y);
            fma2(acc[2][0], a1.x, b0.x); fma2(acc[2][1], a1.x, b0.y);
            fma2(acc[2][2], a1.x, b1.x); fma2(acc[2][3], a1.x, b1.y);
            fma2(acc[3][0], a1.y, b0.x); fma2(acc[3][1], a1.y, b0.y);
            fma2(acc[3][2], a1.y, b1.x); fma2(acc[3][3], a1.y, b1.y);
        }
        __syncthreads();
    }

    // NOTE: pair pi holds nodes (ty*8 + 2*pi) in lo, (+1) in hi.
    // Wait: a pairs are (node, node+1) along the Xs row -> pi covers nodes 2pi,2pi+1.
    float4 bo = make_float4(0.f, 0.f, 0.f, 0.f);
    if (OBIAS) bo = *reinterpret_cast<const float4*>(ob + jn + tx * 4);
#pragma unroll
    for (int pi = 0; pi < 4; pi++) {
        int node0 = nb + ty * 8 + pi * 2;
#pragma unroll
        for (int half = 0; half < 2; half++) {
            int node = node0 + half;
            if (node < n) {
                float4 v;
                v.x = (half ? hi32(acc[pi][0]) : lo32(acc[pi][0])) + bo.x;
                v.y = (half ? hi32(acc[pi][1]) : lo32(acc[pi][1])) + bo.y;
                v.z = (half ? hi32(acc[pi][2]) : lo32(acc[pi][2])) + bo.z;
                v.w = (half ? hi32(acc[pi][3]) : lo32(acc[pi][3])) + bo.w;
                *reinterpret_cast<float4*>(H + (long long)node * KOUT + jn + tx * 4) = v;
            }
        }
    }
}

// ---------------- CSR gather propagation ----------------
__global__ void __launch_bounds__(256)
prop64_kernel(const float* __restrict__ h, float* __restrict__ g, int n)
{
    const int v = (blockIdx.x * blockDim.x + threadIdx.x) >> 5;
    if (v >= n) return;
    const int lane = threadIdx.x & 31;
    const int r0 = g_rowptr[v];
    const int r1 = g_rowptr[v + 1];
    const float di = g_dinv[v];

    float2 acc = *reinterpret_cast<const float2*>(h + (long long)v * F1 + lane * 2);
    acc.x *= di * di;
    acc.y *= di * di;

    int j = r0;
    const int nfull = r0 + ((r1 - r0) & ~3);
    for (; j < nfull; j += 4) {
        int2 e0 = g_edge[j], e1 = g_edge[j + 1], e2 = g_edge[j + 2], e3 = g_edge[j + 3];
        float2 v0 = *reinterpret_cast<const float2*>(h + (long long)e0.x * F1 + lane * 2);
        float2 v1 = *reinterpret_cast<const float2*>(h + (long long)e1.x * F1 + lane * 2);
        float2 v2 = *reinterpret_cast<const float2*>(h + (long long)e2.x * F1 + lane * 2);
        float2 v3 = *reinterpret_cast<const float2*>(h + (long long)e3.x * F1 + lane * 2);
        float w0 = __int_as_float(e0.y), w1 = __int_as_float(e1.y);
        float w2 = __int_as_float(e2.y), w3 = __int_as_float(e3.y);
        acc.x += w0 * v0.x; acc.y += w0 * v0.y;
        acc.x += w1 * v1.x; acc.y += w1 * v1.y;
        acc.x += w2 * v2.x; acc.y += w2 * v2.y;
        acc.x += w3 * v3.x; acc.y += w3 * v3.y;
    }
    for (; j < r1; j++) {
        int2 e = g_edge[j];
        float2 vv = *reinterpret_cast<const float2*>(h + (long long)e.x * F1 + lane * 2);
        float w = __int_as_float(e.y);
        acc.x += w * vv.x; acc.y += w * vv.y;
    }
    *reinterpret_cast<float2*>(g + (long long)v * F1 + lane * 2) = acc;
}

__global__ void __launch_bounds__(256)
prop32_kernel(const float* __restrict__ h, float* __restrict__ g, int n)
{
    const int v = (blockIdx.x * blockDim.x + threadIdx.x) >> 5;
    if (v >= n) return;
    const int lane = threadIdx.x & 31;
    const int r0 = g_rowptr[v];
    const int r1 = g_rowptr[v + 1];
    const float di = g_dinv[v];

    float acc = di * di * h[(long long)v * F2 + lane];

    int j = r0;
    const int nfull = r0 + ((r1 - r0) & ~3);
    for (; j < nfull; j += 4) {
        int2 e0 = g_edge[j], e1 = g_edge[j + 1], e2 = g_edge[j + 2], e3 = g_edge[j + 3];
        float v0 = h[(long long)e0.x * F2 + lane];
        float v1 = h[(long long)e1.x * F2 + lane];
        float v2 = h[(long long)e2.x * F2 + lane];
        float v3 = h[(long long)e3.x * F2 + lane];
        acc += __int_as_float(e0.y) * v0;
        acc += __int_as_float(e1.y) * v1;
        acc += __int_as_float(e2.y) * v2;
        acc += __int_as_float(e3.y) * v3;
    }
    for (; j < r1; j++) {
        int2 e = g_edge[j];
        acc += __int_as_float(e.y) * h[(long long)e.x * F2 + lane];
    }
    g[(long long)v * F2 + lane] = acc;
}

// ---------------- launcher ----------------
extern "C" void kernel_launch(void* const* d_in, const int* in_sizes, int n_in,
                              void* d_out, int out_size)
{
    const float* x  = (const float*)d_in[0];
    const int*   ei = (const int*)  d_in[1];
    const float* W1 = (const float*)d_in[2];
    const float* b1 = (const float*)d_in[3];
    const float* W2 = (const float*)d_in[4];
    const float* b2 = (const float*)d_in[5];
    const float* Wl = (const float*)d_in[6];
    const float* bl = (const float*)d_in[7];
    float* out = (float*)d_out;

    const int n = in_sizes[0] / DIN;
    const int E = in_sizes[1] / 2;

    void *ph1, *pa1, *ph2, *pa2;
    cudaGetSymbolAddress(&ph1, g_h1);
    cudaGetSymbolAddress(&pa1, g_a1);
    cudaGetSymbolAddress(&ph2, g_h2);
    cudaGetSymbolAddress(&pa2, g_a2);
    float* h1 = (float*)ph1; float* a1 = (float*)pa1;
    float* h2 = (float*)ph2; float* a2 = (float*)pa2;

    const int nscan = (n + SCAN_ELEM - 1) / SCAN_ELEM;

    detect_zero_kernel<<<(n + 255) / 256, 256>>>(ei, E, n);
    count_kernel<<<(E + 255) / 256, 256>>>(ei, E);
    scan1_kernel<<<nscan, 256>>>(n);
    scan2_kernel<<<1, 64>>>(nscan);
    scan3_kernel<<<nscan, 256>>>(n, E);
    scatter_kernel<<<(E + 255) / 256, 256>>>(ei, E);

    const int nblk = (n + 127) / 128;
    const int pblk = (n * 32 + 255) / 256;

    // layer 1: h1 = x@W1 ; a1 = prop(h1)
    gemm_rt<DIN, F1, 64, false, false><<<dim3(nblk, 1), 256>>>(x, W1, nullptr, nullptr, h1, n);
    prop64_kernel<<<pblk, 256>>>(h1, a1, n);

    // layer 2: h2 = relu(a1+b1)@W2 ; a2 = prop(h2)
    gemm_rt<F1, F2, 32, true, false><<<dim3(nblk, 1), 128>>>(a1, W2, b1, nullptr, h2, n);
    prop32_kernel<<<pblk, 256>>>(h2, a2, n);

    // head: out = relu(a2+b2)@Wl + bl
    gemm_rt<F2, DOUT, 64, true, true><<<dim3(nblk, 2), 256>>>(a2, Wl, b2, bl, out, n);
}

// round 5
// speedup vs baseline: 1.3009x; 1.3009x over previous
#include <cuda_runtime.h>

// ---------------- problem-size constants ----------------
#define NMAX 50000
#define EMAX 800000
#define F1   64
#define F2   32
#define DIN  128
#define DOUT 128

#define SCAN_ELEM 1024

// ---------------- device scratch ----------------
__device__ int   g_cnt[NMAX];
__device__ int   g_rowptr[NMAX + 1];
__device__ int   g_pos[NMAX];
__device__ float g_dinv[NMAX];
__device__ int2  g_edge[EMAX];
__device__ float g_h1[NMAX * F1];
__device__ float g_a1[NMAX * F1];
__device__ float g_h2[NMAX * F2];
__device__ float g_a2[NMAX * F2];
__device__ int   g_is64;
__device__ int   g_bsum[64];

// ---------------- detect dtype + zero counters (merged) ----------------
__global__ void detect_zero_kernel(const int* __restrict__ w, int E, int n) {
    int i = blockIdx.x * blockDim.x + threadIdx.x;
    if (i < n) g_cnt[i] = 0;
    if (blockIdx.x == 0) {
        __shared__ int any_nonzero;
        if (threadIdx.x == 0) any_nonzero = 0;
        __syncthreads();
        int stride = (2 * E) / 512;
        int idx = 2 * (threadIdx.x * stride) + 1;
        if (w[idx] != 0) atomicOr(&any_nonzero, 1);
        __syncthreads();
        if (threadIdx.x == 0) g_is64 = any_nonzero ? 0 : 1;
    }
}

__global__ void count_kernel(const int* __restrict__ w, int E) {
    int e = blockIdx.x * blockDim.x + threadIdx.x;
    if (e >= E) return;
    int d = g_is64 ? w[2 * (E + e)] : w[E + e];
    atomicAdd(&g_cnt[d], 1);
}

// ---- scan phase 1: per-block reduce (1024 elems/block)
__global__ void scan1_kernel(int n) {
    const int tid = threadIdx.x;
    const int base = blockIdx.x * SCAN_ELEM + tid * 4;
    int s = 0;
#pragma unroll
    for (int i = 0; i < 4; i++) {
        int idx = base + i;
        if (idx < n) s += g_cnt[idx];
    }
#pragma unroll
    for (int o = 16; o; o >>= 1) s += __shfl_down_sync(0xffffffffu, s, o);
    __shared__ int ws[8];
    if ((tid & 31) == 0) ws[tid >> 5] = s;
    __syncthreads();
    if (tid < 8) {
        int t = ws[tid];
#pragma unroll
        for (int o = 4; o; o >>= 1) t += __shfl_down_sync(0xffu, t, o);
        if (tid == 0) g_bsum[blockIdx.x] = t;
    }
}

// ---- scan phase 2+3 fused: each block scans the <=64 block sums itself,
//      then does its local scan -> rowptr / pos / dinv
__global__ void scan3_kernel(int n, int E, int nblk) {
    const int tid = threadIdx.x;
    const int lane = tid & 31;
    const int wid = tid >> 5;
    const int base = blockIdx.x * SCAN_ELEM + tid * 4;

    __shared__ int s_boff;
    if (tid < 32) {
        int a0 = (tid < nblk) ? g_bsum[tid] : 0;
        int a1 = (tid + 32 < nblk) ? g_bsum[tid + 32] : 0;
        int x0 = a0, x1 = a1;
#pragma unroll
        for (int o = 1; o < 32; o <<= 1) {
            int y0 = __shfl_up_sync(0xffffffffu, x0, o);
            int y1 = __shfl_up_sync(0xffffffffu, x1, o);
            if (lane >= o) { x0 += y0; x1 += y1; }
        }
        int tot0 = __shfl_sync(0xffffffffu, x0, 31);
        int b = blockIdx.x;
        int incl, own;
        if (b < 32) {
            incl = __shfl_sync(0xffffffffu, x0, b);
            own  = __shfl_sync(0xffffffffu, a0, b);
        } else {
            incl = tot0 + __shfl_sync(0xffffffffu, x1, b - 32);
            own  = __shfl_sync(0xffffffffu, a1, b - 32);
        }
        if (tid == 0) s_boff = incl - own;   // exclusive offset for this block
    }

    int a[4];
    int tsum = 0;
#pragma unroll
    for (int i = 0; i < 4; i++) {
        int idx = base + i;
        a[i] = (idx < n) ? g_cnt[idx] : 0;
        tsum += a[i];
    }
    int x = tsum;
#pragma unroll
    for (int o = 1; o < 32; o <<= 1) {
        int y = __shfl_up_sync(0xffffffffu, x, o);
        if (lane >= o) x += y;
    }
    const int wex = x - tsum;

    __shared__ int ws[8];
    if (lane == 31) ws[wid] = x;
    __syncthreads();
    if (tid < 8) {
        int orig = ws[tid];
        int t = orig;
#pragma unroll
        for (int o = 1; o < 8; o <<= 1) {
            int y = __shfl_up_sync(0xffu, t, o);
            if (tid >= o) t += y;
        }
        ws[tid] = t - orig;
    }
    __syncthreads();

    int run = s_boff + ws[wid] + wex;
#pragma unroll
    for (int i = 0; i < 4; i++) {
        int idx = base + i;
        if (idx < n) {
            g_rowptr[idx] = run;
            g_pos[idx] = run;
            g_dinv[idx] = rsqrtf((float)(a[i] + 1));
        }
        run += a[i];
    }
    if (blockIdx.x == 0 && tid == 0) g_rowptr[n] = E;
}

__global__ void scatter_kernel(const int* __restrict__ w, int E) {
    int e = blockIdx.x * blockDim.x + threadIdx.x;
    if (e >= E) return;
    int s, d;
    if (g_is64) { s = w[2 * e]; d = w[2 * (E + e)]; }
    else        { s = w[e];     d = w[E + e];       }
    float wn = g_dinv[s] * g_dinv[d];
    int p = atomicAdd(&g_pos[d], 1);
    g_edge[p] = make_int2(s, __float_as_int(wn));
}

// ---------------- register-tiled GEMM (round-3 proven version) ----------------
template<int KIN, int KOUT, int TN, bool INACT, bool OBIAS>
__global__ void __launch_bounds__((TN / 4) * 16)
gemm_rt(const float* __restrict__ A, const float* __restrict__ W,
        const float* __restrict__ ib, const float* __restrict__ ob,
        float* __restrict__ H, int n)
{
    constexpr int TM = 64;
    constexpr int TK = (KIN < 32) ? KIN : 32;
    constexpr int NTX = TN / 4;
    constexpr int NTH = NTX * 16;
    constexpr int XPITCH = TM + 4;

    __shared__ float Xs[TK * XPITCH];
    __shared__ float Ws[TK * TN];

    const int tid = threadIdx.x;
    const int tx = tid % NTX;
    const int ty = tid / NTX;
    const int nb = blockIdx.x * TM;
    const int jn = blockIdx.y * TN;
    const int valid = min(TM, n - nb);

    float acc[4][4];
#pragma unroll
    for (int i = 0; i < 4; i++)
#pragma unroll
        for (int j = 0; j < 4; j++) acc[i][j] = 0.0f;

    for (int kt = 0; kt < KIN; kt += TK) {
#pragma unroll
        for (int idx = tid; idx < TM * TK / 4; idx += NTH) {
            int r  = idx / (TK / 4);
            int kq = idx % (TK / 4);
            float4 v = make_float4(0.f, 0.f, 0.f, 0.f);
            if (r < valid)
                v = *reinterpret_cast<const float4*>(
                        A + (long long)(nb + r) * KIN + kt + kq * 4);
            if (INACT) {
                const float4 bb = *reinterpret_cast<const float4*>(ib + kt + kq * 4);
                v.x = fmaxf(v.x + bb.x, 0.f);
                v.y = fmaxf(v.y + bb.y, 0.f);
                v.z = fmaxf(v.z + bb.z, 0.f);
                v.w = fmaxf(v.w + bb.w, 0.f);
            }
            Xs[(kq * 4 + 0) * XPITCH + r] = v.x;
            Xs[(kq * 4 + 1) * XPITCH + r] = v.y;
            Xs[(kq * 4 + 2) * XPITCH + r] = v.z;
            Xs[(kq * 4 + 3) * XPITCH + r] = v.w;
        }
#pragma unroll
        for (int idx = tid; idx < TK * TN / 4; idx += NTH) {
            int kk = idx / (TN / 4);
            int jq = idx % (TN / 4);
            *reinterpret_cast<float4*>(Ws + kk * TN + jq * 4) =
                *reinterpret_cast<const float4*>(
                    W + (long long)(kt + kk) * KOUT + jn + jq * 4);
        }
        __syncthreads();

#pragma unroll
        for (int kk = 0; kk < TK; kk++) {
            const float4 a = *reinterpret_cast<const float4*>(Xs + kk * XPITCH + ty * 4);
            const float4 b = *reinterpret_cast<const float4*>(Ws + kk * TN + tx * 4);
            acc[0][0] += a.x * b.x; acc[0][1] += a.x * b.y; acc[0][2] += a.x * b.z; acc[0][3] += a.x * b.w;
            acc[1][0] += a.y * b.x; acc[1][1] += a.y * b.y; acc[1][2] += a.y * b.z; acc[1][3] += a.y * b.w;
            acc[2][0] += a.z * b.x; acc[2][1] += a.z * b.y; acc[2][2] += a.z * b.z; acc[2][3] += a.z * b.w;
            acc[3][0] += a.w * b.x; acc[3][1] += a.w * b.y; acc[3][2] += a.w * b.z; acc[3][3] += a.w * b.w;
        }
        __syncthreads();
    }

    float4 bo = make_float4(0.f, 0.f, 0.f, 0.f);
    if (OBIAS) bo = *reinterpret_cast<const float4*>(ob + jn + tx * 4);
#pragma unroll
    for (int i = 0; i < 4; i++) {
        int node = nb + ty * 4 + i;
        if (node < n) {
            float4 v = make_float4(acc[i][0] + bo.x, acc[i][1] + bo.y,
                                   acc[i][2] + bo.z, acc[i][3] + bo.w);
            *reinterpret_cast<float4*>(H + (long long)node * KOUT + jn + tx * 4) = v;
        }
    }
}

// ---------------- CSR gather propagation ----------------
__global__ void __launch_bounds__(256)
prop64_kernel(const float* __restrict__ h, float* __restrict__ g, int n)
{
    const int v = (blockIdx.x * blockDim.x + threadIdx.x) >> 5;
    if (v >= n) return;
    const int lane = threadIdx.x & 31;
    const int r0 = g_rowptr[v];
    const int r1 = g_rowptr[v + 1];
    const float di = g_dinv[v];

    float2 acc = *reinterpret_cast<const float2*>(h + (long long)v * F1 + lane * 2);
    acc.x *= di * di;
    acc.y *= di * di;

    int j = r0;
    const int nfull = r0 + ((r1 - r0) & ~3);
    for (; j < nfull; j += 4) {
        int2 e0 = g_edge[j], e1 = g_edge[j + 1], e2 = g_edge[j + 2], e3 = g_edge[j + 3];
        float2 v0 = *reinterpret_cast<const float2*>(h + (long long)e0.x * F1 + lane * 2);
        float2 v1 = *reinterpret_cast<const float2*>(h + (long long)e1.x * F1 + lane * 2);
        float2 v2 = *reinterpret_cast<const float2*>(h + (long long)e2.x * F1 + lane * 2);
        float2 v3 = *reinterpret_cast<const float2*>(h + (long long)e3.x * F1 + lane * 2);
        float w0 = __int_as_float(e0.y), w1 = __int_as_float(e1.y);
        float w2 = __int_as_float(e2.y), w3 = __int_as_float(e3.y);
        acc.x += w0 * v0.x; acc.y += w0 * v0.y;
        acc.x += w1 * v1.x; acc.y += w1 * v1.y;
        acc.x += w2 * v2.x; acc.y += w2 * v2.y;
        acc.x += w3 * v3.x; acc.y += w3 * v3.y;
    }
    for (; j < r1; j++) {
        int2 e = g_edge[j];
        float2 vv = *reinterpret_cast<const float2*>(h + (long long)e.x * F1 + lane * 2);
        float w = __int_as_float(e.y);
        acc.x += w * vv.x; acc.y += w * vv.y;
    }
    *reinterpret_cast<float2*>(g + (long long)v * F1 + lane * 2) = acc;
}

__global__ void __launch_bounds__(256)
prop32_kernel(const float* __restrict__ h, float* __restrict__ g, int n)
{
    const int v = (blockIdx.x * blockDim.x + threadIdx.x) >> 5;
    if (v >= n) return;
    const int lane = threadIdx.x & 31;
    const int r0 = g_rowptr[v];
    const int r1 = g_rowptr[v + 1];
    const float di = g_dinv[v];

    float acc = di * di * h[(long long)v * F2 + lane];

    int j = r0;
    const int nfull = r0 + ((r1 - r0) & ~3);
    for (; j < nfull; j += 4) {
        int2 e0 = g_edge[j], e1 = g_edge[j + 1], e2 = g_edge[j + 2], e3 = g_edge[j + 3];
        float v0 = h[(long long)e0.x * F2 + lane];
        float v1 = h[(long long)e1.x * F2 + lane];
        float v2 = h[(long long)e2.x * F2 + lane];
        float v3 = h[(long long)e3.x * F2 + lane];
        acc += __int_as_float(e0.y) * v0;
        acc += __int_as_float(e1.y) * v1;
        acc += __int_as_float(e2.y) * v2;
        acc += __int_as_float(e3.y) * v3;
    }
    for (; j < r1; j++) {
        int2 e = g_edge[j];
        acc += __int_as_float(e.y) * h[(long long)e.x * F2 + lane];
    }
    g[(long long)v * F2 + lane] = acc;
}

// ---------------- launcher (forked-stream capture) ----------------
extern "C" void kernel_launch(void* const* d_in, const int* in_sizes, int n_in,
                              void* d_out, int out_size)
{
    const float* x  = (const float*)d_in[0];
    const int*   ei = (const int*)  d_in[1];
    const float* W1 = (const float*)d_in[2];
    const float* b1 = (const float*)d_in[3];
    const float* W2 = (const float*)d_in[4];
    const float* b2 = (const float*)d_in[5];
    const float* Wl = (const float*)d_in[6];
    const float* bl = (const float*)d_in[7];
    float* out = (float*)d_out;

    const int n = in_sizes[0] / DIN;
    const int E = in_sizes[1] / 2;

    void *ph1, *pa1, *ph2, *pa2;
    cudaGetSymbolAddress(&ph1, g_h1);
    cudaGetSymbolAddress(&pa1, g_a1);
    cudaGetSymbolAddress(&ph2, g_h2);
    cudaGetSymbolAddress(&pa2, g_a2);
    float* h1 = (float*)ph1; float* a1 = (float*)pa1;
    float* h2 = (float*)ph2; float* a2 = (float*)pa2;

    const int nscan = (n + SCAN_ELEM - 1) / SCAN_ELEM;
    const int nblk = (n + 63) / 64;
    const int pblk = (n * 32 + 255) / 256;

    // side stream + fork/join events (host objects only; no device memory)
    cudaStream_t s2;
    cudaStreamCreateWithFlags(&s2, cudaStreamNonBlocking);
    cudaEvent_t evFork, evJoin;
    cudaEventCreateWithFlags(&evFork, cudaEventDisableTiming);
    cudaEventCreateWithFlags(&evJoin, cudaEventDisableTiming);

    // fork: CSR build on s2, concurrent with gemm1 on the main stream
    cudaEventRecord(evFork, 0);
    cudaStreamWaitEvent(s2, evFork, 0);

    detect_zero_kernel<<<(n + 255) / 256, 256, 0, s2>>>(ei, E, n);
    count_kernel<<<(E + 255) / 256, 256, 0, s2>>>(ei, E);
    scan1_kernel<<<nscan, 256, 0, s2>>>(n);
    scan3_kernel<<<nscan, 256, 0, s2>>>(n, E, nscan);
    scatter_kernel<<<(E + 255) / 256, 256, 0, s2>>>(ei, E);
    cudaEventRecord(evJoin, s2);

    // main stream: layer-1 GEMM overlaps CSR build
    gemm_rt<DIN, F1, 64, false, false><<<dim3(nblk, 1), 256>>>(x, W1, nullptr, nullptr, h1, n);

    // join: propagation needs both gemm1 and CSR
    cudaStreamWaitEvent(0, evJoin, 0);

    prop64_kernel<<<pblk, 256>>>(h1, a1, n);
    gemm_rt<F1, F2, 32, true, false><<<dim3(nblk, 1), 128>>>(a1, W2, b1, nullptr, h2, n);
    prop32_kernel<<<pblk, 256>>>(h2, a2, n);
    gemm_rt<F2, DOUT, 64, true, true><<<dim3(nblk, 2), 256>>>(a2, Wl, b2, bl, out, n);

    cudaEventDestroy(evFork);
    cudaEventDestroy(evJoin);
    cudaStreamDestroy(s2);
}